// round 3
// baseline (speedup 1.0000x reference)
#include <cuda_runtime.h>
#include <math.h>

// Problem constants
#define N_POINTS 4096
#define N_VIEWS  4
#define IMG_H    128
#define IMG_W    128
#define TOPK     5
#define R2F      0.0004f     // 0.02^2
#define RADF     0.02f

// Tile binning: 16x16 tiles of 8x8 pixels
#define TILE 8
#define NTX  16
#define NTY  16
#define CAP  512             // per-bin capacity (expected max ~150)

// cos(15deg), sin(15deg)
#define CE 0.96592582628906831f
#define SE 0.25881904510252074f

// Camera axes per view (columns of R): X_view = pcd . axis + T, T = (0,0,1.5)
__constant__ float c_ax[N_VIEWS][3] = {
    {-1.f, 0.f, 0.f}, {0.f, 0.f, 1.f}, {1.f, 0.f, 0.f}, {0.f, 0.f, -1.f}};
__constant__ float c_ay[N_VIEWS][3] = {
    {0.f, CE, -SE}, {-SE, CE, 0.f}, {0.f, CE, SE}, {SE, CE, 0.f}};
__constant__ float c_az[N_VIEWS][3] = {
    {0.f, -SE, -CE}, {-CE, -SE, 0.f}, {0.f, -SE, CE}, {CE, -SE, 0.f}};

// Per-view per-tile candidate bins: (px, py, pz_ndc, color)
__device__ float4 g_bins[N_VIEWS][NTY][NTX][CAP];
__device__ int    g_cnt[N_VIEWS][NTY][NTX];   // zero-init at load; raster resets after use

__global__ void prep_kernel(const float* __restrict__ pcd,
                            const float* __restrict__ displace,
                            const float* __restrict__ init_colors,
                            float* __restrict__ out_colors) {
    int n = blockIdx.x * blockDim.x + threadIdx.x;
    if (n >= N_POINTS) return;
    float x = pcd[3 * n + 0];
    float y = pcd[3 * n + 1];
    float z = pcd[3 * n + 2];
    float col = 1.0f / (1.0f + expf(-(init_colors[n] + displace[n])));
    out_colors[n] = col;

    const float rexp = 0.0201f;   // radius + epsilon (conservative bbox)
#pragma unroll
    for (int v = 0; v < N_VIEWS; v++) {
        float px = x * c_ax[v][0] + y * c_ax[v][1] + z * c_ax[v][2];
        float py = x * c_ay[v][0] + y * c_ay[v][1] + z * c_ay[v][2];
        float zv = x * c_az[v][0] + y * c_az[v][1] + z * c_az[v][2] + 1.5f;
        float pz = (zv - 0.01f) / 99.99f;
        if (pz <= 0.0f) continue;

        // pixel index range covered by the disk: xi s.t. |xf(xi) - px| <= r
        // xf(xi) = 1 - (2xi+1)/128  =>  xi in [(1-px-r)*64-0.5, (1-px+r)*64-0.5]
        float xlo_f = (1.0f - px - rexp) * 64.0f - 0.5f;
        float xhi_f = (1.0f - px + rexp) * 64.0f - 0.5f;
        float ylo_f = (1.0f - py - rexp) * 64.0f - 0.5f;
        float yhi_f = (1.0f - py + rexp) * 64.0f - 0.5f;
        int ilo = max(0,   (int)ceilf(xlo_f));
        int ihi = min(127, (int)floorf(xhi_f));
        int jlo = max(0,   (int)ceilf(ylo_f));
        int jhi = min(127, (int)floorf(yhi_f));
        if (ilo > ihi || jlo > jhi) continue;

        int txlo = ilo >> 3, txhi = ihi >> 3;
        int tylo = jlo >> 3, tyhi = jhi >> 3;
        float4 rec = make_float4(px, py, pz, col);
        for (int ty = tylo; ty <= tyhi; ty++)
            for (int tx = txlo; tx <= txhi; tx++) {
                int s = atomicAdd(&g_cnt[v][ty][tx], 1);
                if (s < CAP) g_bins[v][ty][tx][s] = rec;
            }
    }
}

__global__ void __launch_bounds__(64) raster_kernel(float* __restrict__ out) {
    const int v  = blockIdx.z;
    const int tx = blockIdx.x;
    const int ty = blockIdx.y;
    const int tid = threadIdx.y * TILE + threadIdx.x;

    int m = g_cnt[v][ty][tx];
    __syncthreads();
    if (tid == 0) g_cnt[v][ty][tx] = 0;   // reset for next graph replay
    if (m > CAP) m = CAP;

    const int xi = tx * TILE + threadIdx.x;
    const int yi = ty * TILE + threadIdx.y;
    const float inv128 = 0.0078125f;
    const float xf = 1.0f - (float)(2 * xi + 1) * inv128;
    const float yf = 1.0f - (float)(2 * yi + 1) * inv128;

    const float INF = __int_as_float(0x7f800000);
    float zk[TOPK], ak[TOPK], ck[TOPK];
#pragma unroll
    for (int k = 0; k < TOPK; k++) { zk[k] = INF; ak[k] = 0.0f; ck[k] = 0.0f; }

    const float4* __restrict__ cand = g_bins[v][ty][tx];
#pragma unroll 4
    for (int j = 0; j < m; j++) {
        float4 p = __ldg(&cand[j]);
        float dx = p.x - xf;
        float dy = p.y - yf;
        float d2 = dx * dx + dy * dy;
        if (d2 < R2F) {
            float nz = p.z;
            float na = 1.0f - d2 / R2F;
            float nc = p.w;
            // sorted insertion by z ascending (keep 5 smallest)
#pragma unroll
            for (int k = 0; k < TOPK; k++) {
                if (nz < zk[k]) {
                    float t;
                    t = zk[k]; zk[k] = nz; nz = t;
                    t = ak[k]; ak[k] = na; na = t;
                    t = ck[k]; ck[k] = nc; nc = t;
                }
            }
        }
    }

    // Front-to-back over-composite (empty slots contribute 0)
    float trans = 1.0f, pix = 0.0f;
#pragma unroll
    for (int k = 0; k < TOPK; k++) {
        pix += ak[k] * trans * ck[k];
        trans *= (1.0f - ak[k]);
    }

    int base = (((v * IMG_H) + yi) * IMG_W + xi) * 3;
    out[base + 0] = pix;
    out[base + 1] = pix;
    out[base + 2] = pix;
}

extern "C" void kernel_launch(void* const* d_in, const int* in_sizes, int n_in,
                              void* d_out, int out_size) {
    const float* pcd         = (const float*)d_in[0];
    const float* displace    = (const float*)d_in[1];
    const float* init_colors = (const float*)d_in[2];
    float* out = (float*)d_out;

    // colors_ tail lives after the 4*128*128*3 image block
    float* out_colors = out + (size_t)N_VIEWS * IMG_H * IMG_W * 3;

    prep_kernel<<<(N_POINTS + 255) / 256, 256>>>(pcd, displace, init_colors, out_colors);

    dim3 grid(NTX, NTY, N_VIEWS);
    dim3 block(TILE, TILE);
    raster_kernel<<<grid, block>>>(out);
}

// round 4
// speedup vs baseline: 1.2699x; 1.2699x over previous
#include <cuda_runtime.h>
#include <math.h>

// Problem constants
#define N_POINTS 4096
#define N_VIEWS  4
#define IMG_H    128
#define IMG_W    128
#define TOPK     5
#define R2F      0.0004f     // 0.02^2

// Tile binning: 16x16 tiles of 8x8 pixels
#define TILE 8
#define NTX  16
#define NTY  16
#define CAP  384             // per-bin capacity (expected max ~150)

// cos(15deg), sin(15deg)
#define CE 0.96592582628906831f
#define SE 0.25881904510252074f

// Camera axes per view (columns of R): X_view = pcd . axis + T, T = (0,0,1.5)
__constant__ float c_ax[N_VIEWS][3] = {
    {-1.f, 0.f, 0.f}, {0.f, 0.f, 1.f}, {1.f, 0.f, 0.f}, {0.f, 0.f, -1.f}};
__constant__ float c_ay[N_VIEWS][3] = {
    {0.f, CE, -SE}, {-SE, CE, 0.f}, {0.f, CE, SE}, {SE, CE, 0.f}};
__constant__ float c_az[N_VIEWS][3] = {
    {0.f, -SE, -CE}, {-CE, -SE, 0.f}, {0.f, -SE, CE}, {CE, -SE, 0.f}};

// Per-view per-tile candidate bins: (px, py, pz_ndc, color)
__device__ float4 g_bins[N_VIEWS][NTY][NTX][CAP];
__device__ int    g_cnt[N_VIEWS][NTY][NTX];   // zero-init at load; raster resets after use

__global__ void prep_kernel(const float* __restrict__ pcd,
                            const float* __restrict__ displace,
                            const float* __restrict__ init_colors,
                            float* __restrict__ out_colors) {
    int n = blockIdx.x * blockDim.x + threadIdx.x;
    if (n >= N_POINTS) return;
    float x = pcd[3 * n + 0];
    float y = pcd[3 * n + 1];
    float z = pcd[3 * n + 2];
    float col = 1.0f / (1.0f + expf(-(init_colors[n] + displace[n])));
    out_colors[n] = col;

    const float rexp = 0.0201f;   // radius + epsilon (conservative bbox)
#pragma unroll
    for (int v = 0; v < N_VIEWS; v++) {
        float px = x * c_ax[v][0] + y * c_ax[v][1] + z * c_ax[v][2];
        float py = x * c_ay[v][0] + y * c_ay[v][1] + z * c_ay[v][2];
        float zv = x * c_az[v][0] + y * c_az[v][1] + z * c_az[v][2] + 1.5f;
        float pz = (zv - 0.01f) / 99.99f;
        if (pz <= 0.0f) continue;

        // pixel range covered: xf(xi) = 1 - (2xi+1)/128 => xi in [(1-px-r)*64-.5, (1-px+r)*64-.5]
        float xlo_f = (1.0f - px - rexp) * 64.0f - 0.5f;
        float xhi_f = (1.0f - px + rexp) * 64.0f - 0.5f;
        float ylo_f = (1.0f - py - rexp) * 64.0f - 0.5f;
        float yhi_f = (1.0f - py + rexp) * 64.0f - 0.5f;
        int ilo = max(0,   (int)ceilf(xlo_f));
        int ihi = min(127, (int)floorf(xhi_f));
        int jlo = max(0,   (int)ceilf(ylo_f));
        int jhi = min(127, (int)floorf(yhi_f));
        if (ilo > ihi || jlo > jhi) continue;

        int txlo = ilo >> 3, txhi = ihi >> 3;
        int tylo = jlo >> 3, tyhi = jhi >> 3;
        float4 rec = make_float4(px, py, pz, col);
        for (int ty = tylo; ty <= tyhi; ty++)
            for (int tx = txlo; tx <= txhi; tx++) {
                int s = atomicAdd(&g_cnt[v][ty][tx], 1);
                if (s < CAP) g_bins[v][ty][tx][s] = rec;
            }
    }
}

__global__ void __launch_bounds__(64) raster_kernel(float* __restrict__ out) {
    __shared__ float4 s_cand[CAP];

    const int v  = blockIdx.z;
    const int tx = blockIdx.x;
    const int ty = blockIdx.y;
    const int tid = threadIdx.y * TILE + threadIdx.x;

    int m = g_cnt[v][ty][tx];
    if (m > CAP) m = CAP;

    // cooperative coalesced staging of the bin into shared memory
    const float4* __restrict__ cand = g_bins[v][ty][tx];
    for (int j = tid; j < m; j += 64) s_cand[j] = cand[j];
    __syncthreads();
    if (tid == 0) g_cnt[v][ty][tx] = 0;   // reset for next graph replay

    const int xi = tx * TILE + threadIdx.x;
    const int yi = ty * TILE + threadIdx.y;
    const float inv128 = 0.0078125f;
    const float xf = 1.0f - (float)(2 * xi + 1) * inv128;
    const float yf = 1.0f - (float)(2 * yi + 1) * inv128;

    const float INF = __int_as_float(0x7f800000);
    float zk[TOPK], ak[TOPK], ck[TOPK];
#pragma unroll
    for (int k = 0; k < TOPK; k++) { zk[k] = INF; ak[k] = 0.0f; ck[k] = 0.0f; }

    // scan shared candidate list (broadcast LDS, independent iterations)
#pragma unroll 4
    for (int j = 0; j < m; j++) {
        float4 p = s_cand[j];
        float dx = p.x - xf;
        float dy = p.y - yf;
        float d2 = dx * dx + dy * dy;
        if (d2 < R2F) {
            float nz = p.z;
            float na = 1.0f - d2 / R2F;
            float nc = p.w;
            // sorted insertion by z ascending (keep 5 smallest)
#pragma unroll
            for (int k = 0; k < TOPK; k++) {
                if (nz < zk[k]) {
                    float t;
                    t = zk[k]; zk[k] = nz; nz = t;
                    t = ak[k]; ak[k] = na; na = t;
                    t = ck[k]; ck[k] = nc; nc = t;
                }
            }
        }
    }

    // Front-to-back over-composite (empty slots contribute 0)
    float trans = 1.0f, pix = 0.0f;
#pragma unroll
    for (int k = 0; k < TOPK; k++) {
        pix += ak[k] * trans * ck[k];
        trans *= (1.0f - ak[k]);
    }

    int base = (((v * IMG_H) + yi) * IMG_W + xi) * 3;
    out[base + 0] = pix;
    out[base + 1] = pix;
    out[base + 2] = pix;
}

extern "C" void kernel_launch(void* const* d_in, const int* in_sizes, int n_in,
                              void* d_out, int out_size) {
    const float* pcd         = (const float*)d_in[0];
    const float* displace    = (const float*)d_in[1];
    const float* init_colors = (const float*)d_in[2];
    float* out = (float*)d_out;

    // colors_ tail lives after the 4*128*128*3 image block
    float* out_colors = out + (size_t)N_VIEWS * IMG_H * IMG_W * 3;

    prep_kernel<<<(N_POINTS + 127) / 128, 128>>>(pcd, displace, init_colors, out_colors);

    dim3 grid(NTX, NTY, N_VIEWS);
    dim3 block(TILE, TILE);
    raster_kernel<<<grid, block>>>(out);
}

// round 5
// speedup vs baseline: 1.3633x; 1.0736x over previous
#include <cuda_runtime.h>
#include <math.h>

// Problem constants
#define N_POINTS 4096
#define N_VIEWS  4
#define IMG_H    128
#define IMG_W    128
#define TOPK     5
#define R2F      0.0004f     // 0.02^2

// Tile binning: 16x16 tiles of 8x8 pixels
#define TILE   8
#define NTX    16
#define NTY    16
#define CAP    384           // per-bin capacity (expected max ~150)
#define SLICES 4             // candidate-scan parallelism per tile

// cos(15deg), sin(15deg)
#define CE 0.96592582628906831f
#define SE 0.25881904510252074f

// Camera axes per view (columns of R): X_view = pcd . axis + T, T = (0,0,1.5)
__constant__ float c_ax[N_VIEWS][3] = {
    {-1.f, 0.f, 0.f}, {0.f, 0.f, 1.f}, {1.f, 0.f, 0.f}, {0.f, 0.f, -1.f}};
__constant__ float c_ay[N_VIEWS][3] = {
    {0.f, CE, -SE}, {-SE, CE, 0.f}, {0.f, CE, SE}, {SE, CE, 0.f}};
__constant__ float c_az[N_VIEWS][3] = {
    {0.f, -SE, -CE}, {-CE, -SE, 0.f}, {0.f, -SE, CE}, {CE, -SE, 0.f}};

// Per-view per-tile candidate bins: (px, py, pz_ndc, color)
__device__ float4 g_bins[N_VIEWS][NTY][NTX][CAP];
__device__ int    g_cnt[N_VIEWS][NTY][NTX];   // zero-init at load; raster resets after use

__global__ void prep_kernel(const float* __restrict__ pcd,
                            const float* __restrict__ displace,
                            const float* __restrict__ init_colors,
                            float* __restrict__ out_colors) {
    int n = blockIdx.x * blockDim.x + threadIdx.x;
    if (n >= N_POINTS) return;
    float x = pcd[3 * n + 0];
    float y = pcd[3 * n + 1];
    float z = pcd[3 * n + 2];
    float col = 1.0f / (1.0f + expf(-(init_colors[n] + displace[n])));
    out_colors[n] = col;

    const float rexp = 0.0201f;   // radius + epsilon (conservative bbox)
#pragma unroll
    for (int v = 0; v < N_VIEWS; v++) {
        float px = x * c_ax[v][0] + y * c_ax[v][1] + z * c_ax[v][2];
        float py = x * c_ay[v][0] + y * c_ay[v][1] + z * c_ay[v][2];
        float zv = x * c_az[v][0] + y * c_az[v][1] + z * c_az[v][2] + 1.5f;
        float pz = (zv - 0.01f) / 99.99f;
        if (pz <= 0.0f) continue;

        // pixel range: xf(xi) = 1 - (2xi+1)/128 => xi in [(1-px-r)*64-.5, (1-px+r)*64-.5]
        float xlo_f = (1.0f - px - rexp) * 64.0f - 0.5f;
        float xhi_f = (1.0f - px + rexp) * 64.0f - 0.5f;
        float ylo_f = (1.0f - py - rexp) * 64.0f - 0.5f;
        float yhi_f = (1.0f - py + rexp) * 64.0f - 0.5f;
        int ilo = max(0,   (int)ceilf(xlo_f));
        int ihi = min(127, (int)floorf(xhi_f));
        int jlo = max(0,   (int)ceilf(ylo_f));
        int jhi = min(127, (int)floorf(yhi_f));
        if (ilo > ihi || jlo > jhi) continue;

        int txlo = ilo >> 3, txhi = ihi >> 3;
        int tylo = jlo >> 3, tyhi = jhi >> 3;
        float4 rec = make_float4(px, py, pz, col);
        for (int ty = tylo; ty <= tyhi; ty++)
            for (int tx = txlo; tx <= txhi; tx++) {
                int s = atomicAdd(&g_cnt[v][ty][tx], 1);
                if (s < CAP) g_bins[v][ty][tx][s] = rec;
            }
    }
}

__global__ void __launch_bounds__(TILE * TILE * SLICES)
raster_kernel(float* __restrict__ out) {
    __shared__ float4 s_cand[CAP];
    __shared__ float s_z[SLICES][TILE * TILE][TOPK];
    __shared__ float s_a[SLICES][TILE * TILE][TOPK];
    __shared__ float s_c[SLICES][TILE * TILE][TOPK];

    const int v   = blockIdx.z;
    const int tx  = blockIdx.x;
    const int ty  = blockIdx.y;
    const int pix = threadIdx.y * TILE + threadIdx.x;   // 0..63
    const int sl  = threadIdx.z;                        // 0..3 (uniform per warp)
    const int tid = sl * (TILE * TILE) + pix;

    int m = g_cnt[v][ty][tx];
    if (m > CAP) m = CAP;

    // cooperative coalesced staging of the bin into shared memory
    const float4* __restrict__ cand = g_bins[v][ty][tx];
    for (int j = tid; j < m; j += TILE * TILE * SLICES) s_cand[j] = cand[j];
    __syncthreads();
    if (tid == 0) g_cnt[v][ty][tx] = 0;   // reset for next graph replay

    const int xi = tx * TILE + threadIdx.x;
    const int yi = ty * TILE + threadIdx.y;
    const float inv128 = 0.0078125f;
    const float xf = 1.0f - (float)(2 * xi + 1) * inv128;
    const float yf = 1.0f - (float)(2 * yi + 1) * inv128;

    const float INF = __int_as_float(0x7f800000);
    float zk[TOPK], ak[TOPK], ck[TOPK];
#pragma unroll
    for (int k = 0; k < TOPK; k++) { zk[k] = INF; ak[k] = 0.0f; ck[k] = 0.0f; }

    // sliced scan: slice sl handles candidates sl, sl+4, sl+8, ...
#pragma unroll 2
    for (int j = sl; j < m; j += SLICES) {
        float4 p = s_cand[j];
        float dx = p.x - xf;
        float dy = p.y - yf;
        float d2 = dx * dx + dy * dy;
        if (d2 < R2F) {
            float nz = p.z;
            float na = 1.0f - d2 / R2F;
            float nc = p.w;
#pragma unroll
            for (int k = 0; k < TOPK; k++) {
                if (nz < zk[k]) {
                    float t;
                    t = zk[k]; zk[k] = nz; nz = t;
                    t = ak[k]; ak[k] = na; na = t;
                    t = ck[k]; ck[k] = nc; nc = t;
                }
            }
        }
    }

    // publish per-slice partial top-5
#pragma unroll
    for (int k = 0; k < TOPK; k++) {
        s_z[sl][pix][k] = zk[k];
        s_a[sl][pix][k] = ak[k];
        s_c[sl][pix][k] = ck[k];
    }
    __syncthreads();

    // slice 0 merges the 4 partial lists (20 entries; INF-padded entries have a=0)
    if (sl == 0) {
        float mz[TOPK], ma[TOPK], mc[TOPK];
#pragma unroll
        for (int k = 0; k < TOPK; k++) { mz[k] = INF; ma[k] = 0.0f; mc[k] = 0.0f; }
#pragma unroll
        for (int s = 0; s < SLICES; s++) {
#pragma unroll
            for (int e = 0; e < TOPK; e++) {
                float nz = s_z[s][pix][e];
                float na = s_a[s][pix][e];
                float nc = s_c[s][pix][e];
#pragma unroll
                for (int k = 0; k < TOPK; k++) {
                    if (nz < mz[k]) {
                        float t;
                        t = mz[k]; mz[k] = nz; nz = t;
                        t = ma[k]; ma[k] = na; na = t;
                        t = mc[k]; mc[k] = nc; nc = t;
                    }
                }
            }
        }

        // front-to-back over-composite (empty slots contribute 0)
        float trans = 1.0f, pixv = 0.0f;
#pragma unroll
        for (int k = 0; k < TOPK; k++) {
            pixv += ma[k] * trans * mc[k];
            trans *= (1.0f - ma[k]);
        }

        int base = (((v * IMG_H) + yi) * IMG_W + xi) * 3;
        out[base + 0] = pixv;
        out[base + 1] = pixv;
        out[base + 2] = pixv;
    }
}

extern "C" void kernel_launch(void* const* d_in, const int* in_sizes, int n_in,
                              void* d_out, int out_size) {
    const float* pcd         = (const float*)d_in[0];
    const float* displace    = (const float*)d_in[1];
    const float* init_colors = (const float*)d_in[2];
    float* out = (float*)d_out;

    // colors_ tail lives after the 4*128*128*3 image block
    float* out_colors = out + (size_t)N_VIEWS * IMG_H * IMG_W * 3;

    prep_kernel<<<(N_POINTS + 127) / 128, 128>>>(pcd, displace, init_colors, out_colors);

    dim3 grid(NTX, NTY, N_VIEWS);
    dim3 block(TILE, TILE, SLICES);
    raster_kernel<<<grid, block>>>(out);
}

// round 6
// speedup vs baseline: 1.9450x; 1.4267x over previous
#include <cuda_runtime.h>
#include <math.h>

// Problem constants
#define N_POINTS 4096
#define N_VIEWS  4
#define IMG_H    128
#define IMG_W    128
#define TOPK     5
#define R2F      0.0004f     // 0.02^2

// Tile binning: 16x16 tiles of 8x8 pixels
#define TILE   8
#define NTX    16
#define NTY    16
#define CAP    384           // per-bin capacity (expected max ~150)
#define SLICES 4             // candidate-scan parallelism per pixel

// cos(15deg), sin(15deg)
#define CE 0.96592582628906831f
#define SE 0.25881904510252074f

// Camera axes per view (columns of R): X_view = pcd . axis + T, T = (0,0,1.5)
__constant__ float c_ax[N_VIEWS][3] = {
    {-1.f, 0.f, 0.f}, {0.f, 0.f, 1.f}, {1.f, 0.f, 0.f}, {0.f, 0.f, -1.f}};
__constant__ float c_ay[N_VIEWS][3] = {
    {0.f, CE, -SE}, {-SE, CE, 0.f}, {0.f, CE, SE}, {SE, CE, 0.f}};
__constant__ float c_az[N_VIEWS][3] = {
    {0.f, -SE, -CE}, {-CE, -SE, 0.f}, {0.f, -SE, CE}, {CE, -SE, 0.f}};

// Per-view per-tile candidate bins: (px, py, pz_ndc, color)
__device__ float4 g_bins[N_VIEWS][NTY][NTX][CAP];
__device__ int    g_cnt[N_VIEWS][NTY][NTX];   // zero-init at load; raster resets after use

// One thread per (point, view). 4 consecutive threads share a point (broadcast loads).
__global__ void prep_kernel(const float* __restrict__ pcd,
                            const float* __restrict__ displace,
                            const float* __restrict__ init_colors,
                            float* __restrict__ out_colors) {
    int t = blockIdx.x * blockDim.x + threadIdx.x;
    if (t >= N_POINTS * N_VIEWS) return;
    int n = t >> 2;
    int v = t & 3;

    float x = pcd[3 * n + 0];
    float y = pcd[3 * n + 1];
    float z = pcd[3 * n + 2];
    float col = 1.0f / (1.0f + expf(-(init_colors[n] + displace[n])));
    if (v == 0) out_colors[n] = col;

    float px = x * c_ax[v][0] + y * c_ax[v][1] + z * c_ax[v][2];
    float py = x * c_ay[v][0] + y * c_ay[v][1] + z * c_ay[v][2];
    float zv = x * c_az[v][0] + y * c_az[v][1] + z * c_az[v][2] + 1.5f;
    float pz = (zv - 0.01f) / 99.99f;
    if (pz <= 0.0f) return;

    // pixel range covered: xf(xi) = 1 - (2xi+1)/128 => xi in [(1-px-r)*64-.5, (1-px+r)*64-.5]
    const float rexp = 0.0201f;   // radius + epsilon (conservative bbox)
    float xlo_f = (1.0f - px - rexp) * 64.0f - 0.5f;
    float xhi_f = (1.0f - px + rexp) * 64.0f - 0.5f;
    float ylo_f = (1.0f - py - rexp) * 64.0f - 0.5f;
    float yhi_f = (1.0f - py + rexp) * 64.0f - 0.5f;
    int ilo = max(0,   (int)ceilf(xlo_f));
    int ihi = min(127, (int)floorf(xhi_f));
    int jlo = max(0,   (int)ceilf(ylo_f));
    int jhi = min(127, (int)floorf(yhi_f));
    if (ilo > ihi || jlo > jhi) return;

    // disk spans at most 3 pixels per axis -> at most 2 tiles per axis
    int txlo = ilo >> 3, txhi = ihi >> 3;
    int tylo = jlo >> 3, tyhi = jhi >> 3;
    bool x2 = (txhi != txlo);
    bool y2 = (tyhi != tylo);
    float4 rec = make_float4(px, py, pz, col);

    // Independent atomics (latency overlapped), then predicated stores
    int s00 =              atomicAdd(&g_cnt[v][tylo][txlo], 1);
    int s01 = x2         ? atomicAdd(&g_cnt[v][tylo][txhi], 1) : CAP;
    int s10 = y2         ? atomicAdd(&g_cnt[v][tyhi][txlo], 1) : CAP;
    int s11 = (x2 && y2) ? atomicAdd(&g_cnt[v][tyhi][txhi], 1) : CAP;
    if (s00 < CAP) g_bins[v][tylo][txlo][s00] = rec;
    if (s01 < CAP) g_bins[v][tylo][txhi][s01] = rec;
    if (s10 < CAP) g_bins[v][tyhi][txlo][s10] = rec;
    if (s11 < CAP) g_bins[v][tyhi][txhi][s11] = rec;
}

// blockDim = (SLICES, 64): threadIdx.x = slice (adjacent lanes), threadIdx.y = pixel
__global__ void __launch_bounds__(TILE * TILE * SLICES)
raster_kernel(float* __restrict__ out) {
    __shared__ float4 s_cand[CAP];

    const int v   = blockIdx.z;
    const int tx  = blockIdx.x;
    const int ty  = blockIdx.y;
    const int sl  = threadIdx.x;            // 0..3
    const int pix = threadIdx.y;            // 0..63
    const int tid = pix * SLICES + sl;

    int m = g_cnt[v][ty][tx];
    if (m > CAP) m = CAP;

    // cooperative coalesced staging of the bin into shared memory
    const float4* __restrict__ cand = g_bins[v][ty][tx];
    for (int j = tid; j < m; j += TILE * TILE * SLICES) s_cand[j] = cand[j];
    __syncthreads();
    if (tid == 0) g_cnt[v][ty][tx] = 0;   // reset for next graph replay

    const int xi = tx * TILE + (pix & 7);
    const int yi = ty * TILE + (pix >> 3);
    const float inv128 = 0.0078125f;
    const float xf = 1.0f - (float)(2 * xi + 1) * inv128;
    const float yf = 1.0f - (float)(2 * yi + 1) * inv128;

    const float INF = __int_as_float(0x7f800000);
    float zk[TOPK], ak[TOPK], ck[TOPK];
#pragma unroll
    for (int k = 0; k < TOPK; k++) { zk[k] = INF; ak[k] = 0.0f; ck[k] = 0.0f; }

    // sliced scan: slice sl handles candidates sl, sl+4, sl+8, ...
#pragma unroll 2
    for (int j = sl; j < m; j += SLICES) {
        float4 p = s_cand[j];
        float dx = p.x - xf;
        float dy = p.y - yf;
        float d2 = dx * dx + dy * dy;
        if (d2 < R2F) {
            float nz = p.z;
            float na = 1.0f - d2 / R2F;
            float nc = p.w;
#pragma unroll
            for (int k = 0; k < TOPK; k++) {
                if (nz < zk[k]) {
                    float t;
                    t = zk[k]; zk[k] = nz; nz = t;
                    t = ak[k]; ak[k] = na; na = t;
                    t = ck[k]; ck[k] = nc; nc = t;
                }
            }
        }
    }

    // butterfly merge across the 4 slice lanes (xor 1, then xor 2);
    // all lanes converge to the same top-5 (INF padding has alpha=0)
#pragma unroll
    for (int st = 1; st <= 2; st <<= 1) {
        float rz[TOPK], ra[TOPK], rc[TOPK];
#pragma unroll
        for (int e = 0; e < TOPK; e++) {
            rz[e] = __shfl_xor_sync(0xffffffffu, zk[e], st);
            ra[e] = __shfl_xor_sync(0xffffffffu, ak[e], st);
            rc[e] = __shfl_xor_sync(0xffffffffu, ck[e], st);
        }
#pragma unroll
        for (int e = 0; e < TOPK; e++) {
            float nz = rz[e], na = ra[e], nc = rc[e];
#pragma unroll
            for (int k = 0; k < TOPK; k++) {
                if (nz < zk[k]) {
                    float t;
                    t = zk[k]; zk[k] = nz; nz = t;
                    t = ak[k]; ak[k] = na; na = t;
                    t = ck[k]; ck[k] = nc; nc = t;
                }
            }
        }
    }

    if (sl == 0) {
        // front-to-back over-composite (empty slots contribute 0)
        float trans = 1.0f, pixv = 0.0f;
#pragma unroll
        for (int k = 0; k < TOPK; k++) {
            pixv += ak[k] * trans * ck[k];
            trans *= (1.0f - ak[k]);
        }

        int base = (((v * IMG_H) + yi) * IMG_W + xi) * 3;
        out[base + 0] = pixv;
        out[base + 1] = pixv;
        out[base + 2] = pixv;
    }
}

extern "C" void kernel_launch(void* const* d_in, const int* in_sizes, int n_in,
                              void* d_out, int out_size) {
    const float* pcd         = (const float*)d_in[0];
    const float* displace    = (const float*)d_in[1];
    const float* init_colors = (const float*)d_in[2];
    float* out = (float*)d_out;

    // colors_ tail lives after the 4*128*128*3 image block
    float* out_colors = out + (size_t)N_VIEWS * IMG_H * IMG_W * 3;

    prep_kernel<<<(N_POINTS * N_VIEWS + 255) / 256, 256>>>(pcd, displace, init_colors, out_colors);

    dim3 grid(NTX, NTY, N_VIEWS);
    dim3 block(SLICES, TILE * TILE);
    raster_kernel<<<grid, block>>>(out);
}